// round 4
// baseline (speedup 1.0000x reference)
#include <cuda_runtime.h>

#define GRID_NUM 7
#define CELLS_PER_IMG 49
#define IMG_SIZE 448.0f
#define GRID_SIZE 64.0f
#define LAMBDA_COORD 5.0f
#define LAMBDA_NOOBJ 0.1f
#define EPSF 1e-12f

#define NTHREADS 256

__device__ double g_acc;            // zero-init in cubin; reset by last block
__device__ unsigned int g_ticket;   // zero-init in cubin; reset by last block

__device__ __forceinline__ float iou_f(float bx, float by, float bw, float bh,
                                       float tx, float ty, float tw, float th,
                                       float gi, float gj) {
    float cx_p = bx * GRID_SIZE + gj * GRID_SIZE;
    float cy_p = by * GRID_SIZE + gi * GRID_SIZE;
    float w_p = bw * IMG_SIZE;
    float h_p = bh * IMG_SIZE;
    float x0p = cx_p - w_p * 0.5f, x1p = cx_p + w_p * 0.5f;
    float y0p = cy_p - h_p * 0.5f, y1p = cy_p + h_p * 0.5f;
    float cx_t = tx * GRID_SIZE + gj * GRID_SIZE;
    float cy_t = ty * GRID_SIZE + gi * GRID_SIZE;
    float w_t = tw * IMG_SIZE;
    float h_t = th * IMG_SIZE;
    float x0t = cx_t - w_t * 0.5f, x1t = cx_t + w_t * 0.5f;
    float y0t = cy_t - h_t * 0.5f;
    float y1t = cy_t + w_t * 0.5f;   // TYPO kept from reference: uses w_t
    float ux0 = fmaxf(x0p, x0t);
    float ux1 = fminf(x1p, x1t);
    float uy0 = fmaxf(y0p, y0t);
    float uy1 = fminf(y1p, y1t);
    bool valid = (ux0 < ux1) && (uy0 < uy1);
    float area_u = (ux1 - ux0) * (uy1 - uy0);
    float area_p = (x1p - x0p) * (y1p - y0p);
    float area_t = (x1t - x0t) * (y1t - y0t);
    float res = area_u / (area_p + area_t - area_u + EPSF);
    return valid ? res : 0.0f;
}

__global__ void __launch_bounds__(NTHREADS)
yolo_loss_fused(const float* __restrict__ y_pre,
                const float* __restrict__ y_true,
                int n_cells, float inv_b, float* __restrict__ out) {
    int tid = threadIdx.x;
    int idx = blockIdx.x * NTHREADS + tid;

    float local = 0.0f;
    if (idx < n_cells) {
        int g = idx % CELLS_PER_IMG;
        float gi = (float)(g / GRID_NUM);
        float gj = (float)(g % GRID_NUM);

        // y_pre cell: 10 floats, 40B stride -> 8B aligned -> float2 loads
        const float2* p = (const float2*)(y_pre + (size_t)idx * 10);
        float2 p01 = p[0];
        float2 p23 = p[1];
        float2 p45 = p[2];
        float2 p67 = p[3];
        float2 p89 = p[4];

        const float* t = y_true + (size_t)idx * 5;
        float t0 = t[0], t1 = t[1], t2 = t[2], t3 = t[3], t4 = t[4];

        float iou0 = iou_f(p01.x, p01.y, p23.x, p23.y, t0, t1, t2, t3, gi, gj);
        float iou1 = iou_f(p45.y, p67.x, p67.y, p89.x, t0, t1, t2, t3, gi, gj);

        bool obj = (t4 == 1.0f);
        bool c0 = iou0 > iou1;

        if (obj) {
            float conf_pre = c0 ? p45.x : p89.y;
            float conf_true = c0 ? iou0 : iou1;
            float dc = conf_pre - conf_true;
            local = dc * dc;
            float xb = c0 ? p01.x : p45.y;
            float yb = c0 ? p01.y : p67.x;
            float dx = xb - t0;
            float dy = yb - t1;
            local += LAMBDA_COORD * (dx * dx + dy * dy);
            float wb = fmaxf(c0 ? p23.x : p67.y, EPSF);
            float hb = fmaxf(c0 ? p23.y : p89.x, EPSF);
            float wt = fmaxf(t2, EPSF);
            float ht = fmaxf(t3, EPSF);
            float dw = sqrtf(wb) - sqrtf(wt);
            float dh = sqrtf(hb) - sqrtf(ht);
            local += LAMBDA_COORD * (dw * dw + dh * dh);
        } else {
            local = LAMBDA_NOOBJ * (p45.x * p45.x + p89.y * p89.y);
        }
    }

    // ---- block reduction (fp32) ----
    #pragma unroll
    for (int off = 16; off > 0; off >>= 1)
        local += __shfl_down_sync(0xFFFFFFFFu, local, off);

    __shared__ float warp_sums[NTHREADS / 32];
    __shared__ bool s_is_last;
    int lane = tid & 31;
    int wid = tid >> 5;
    if (lane == 0) warp_sums[wid] = local;
    __syncthreads();

    if (tid == 0) {
        float v = 0.0f;
        #pragma unroll
        for (int i = 0; i < NTHREADS / 32; i++) v += warp_sums[i];
        atomicAdd(&g_acc, (double)v);
        __threadfence();
        unsigned int prev = atomicInc(&g_ticket, 0xFFFFFFFFu);
        s_is_last = (prev == gridDim.x - 1);
    }
    __syncthreads();

    // ---- last block finalizes & resets state for the next graph replay ----
    if (s_is_last && tid == 0) {
        double v = atomicAdd(&g_acc, 0.0);   // coherent read via L2
        out[0] = (float)(v * (double)inv_b);
        g_acc = 0.0;
        __threadfence();
        g_ticket = 0;
    }
}

extern "C" void kernel_launch(void* const* d_in, const int* in_sizes, int n_in,
                              void* d_out, int out_size) {
    const float* y_pre = (const float*)d_in[0];
    const float* y_true = (const float*)d_in[1];
    float* out = (float*)d_out;

    int n_cells = in_sizes[1] / 5;               // B * 49
    int B = n_cells / CELLS_PER_IMG;

    int grid = (n_cells + NTHREADS - 1) / NTHREADS;   // one cell per thread
    yolo_loss_fused<<<grid, NTHREADS>>>(y_pre, y_true, n_cells,
                                        1.0f / (float)B, out);
}

// round 5
// speedup vs baseline: 1.0432x; 1.0432x over previous
#include <cuda_runtime.h>

#define GRID_NUM 7
#define CELLS_PER_IMG 49
#define IMG_SIZE 448.0f
#define GRID_SIZE 64.0f
#define LAMBDA_COORD 5.0f
#define LAMBDA_NOOBJ 0.1f
#define EPSF 1e-12f

#define NTHREADS 256

__device__ double g_acc;            // zero-init in cubin; reset by last block
__device__ unsigned int g_ticket;   // zero-init in cubin; reset by last block

__device__ __forceinline__ float iou_f(float bx, float by, float bw, float bh,
                                       float tx, float ty, float tw, float th,
                                       float gi, float gj) {
    float cx_p = bx * GRID_SIZE + gj * GRID_SIZE;
    float cy_p = by * GRID_SIZE + gi * GRID_SIZE;
    float w_p = bw * IMG_SIZE;
    float h_p = bh * IMG_SIZE;
    float x0p = cx_p - w_p * 0.5f, x1p = cx_p + w_p * 0.5f;
    float y0p = cy_p - h_p * 0.5f, y1p = cy_p + h_p * 0.5f;
    float cx_t = tx * GRID_SIZE + gj * GRID_SIZE;
    float cy_t = ty * GRID_SIZE + gi * GRID_SIZE;
    float w_t = tw * IMG_SIZE;
    float h_t = th * IMG_SIZE;
    float x0t = cx_t - w_t * 0.5f, x1t = cx_t + w_t * 0.5f;
    float y0t = cy_t - h_t * 0.5f;
    float y1t = cy_t + w_t * 0.5f;   // TYPO kept from reference: uses w_t
    float ux0 = fmaxf(x0p, x0t);
    float ux1 = fminf(x1p, x1t);
    float uy0 = fmaxf(y0p, y0t);
    float uy1 = fminf(y1p, y1t);
    bool valid = (ux0 < ux1) && (uy0 < uy1);
    float area_u = (ux1 - ux0) * (uy1 - uy0);
    float area_p = (x1p - x0p) * (y1p - y0p);
    float area_t = (x1t - x0t) * (y1t - y0t);
    float res = area_u / (area_p + area_t - area_u + EPSF);
    return valid ? res : 0.0f;
}

__device__ __forceinline__ float cell_loss(float p0, float p1, float p2, float p3, float p4,
                                           float p5, float p6, float p7, float p8, float p9,
                                           float t0, float t1, float t2, float t3, float t4,
                                           int cell_idx) {
    int g = cell_idx % CELLS_PER_IMG;
    float gi = (float)(g / GRID_NUM);
    float gj = (float)(g % GRID_NUM);

    float iou0 = iou_f(p0, p1, p2, p3, t0, t1, t2, t3, gi, gj);
    float iou1 = iou_f(p5, p6, p7, p8, t0, t1, t2, t3, gi, gj);

    bool obj = (t4 == 1.0f);
    bool c0 = iou0 > iou1;

    float local;
    if (obj) {
        float conf_pre = c0 ? p4 : p9;
        float conf_true = c0 ? iou0 : iou1;
        float dc = conf_pre - conf_true;
        local = dc * dc;
        float xb = c0 ? p0 : p5;
        float yb = c0 ? p1 : p6;
        float dx = xb - t0;
        float dy = yb - t1;
        local += LAMBDA_COORD * (dx * dx + dy * dy);
        float wb = fmaxf(c0 ? p2 : p7, EPSF);
        float hb = fmaxf(c0 ? p3 : p8, EPSF);
        float wt = fmaxf(t2, EPSF);
        float ht = fmaxf(t3, EPSF);
        float dw = sqrtf(wb) - sqrtf(wt);
        float dh = sqrtf(hb) - sqrtf(ht);
        local += LAMBDA_COORD * (dw * dw + dh * dh);
    } else {
        local = LAMBDA_NOOBJ * (p4 * p4 + p9 * p9);
    }
    return local;
}

__global__ void __launch_bounds__(NTHREADS)
yolo_loss_fused(const float* __restrict__ y_pre,
                const float* __restrict__ y_true,
                int n_cells, float inv_b, float* __restrict__ out) {
    int tid = threadIdx.x;
    int pair = blockIdx.x * NTHREADS + tid;   // each thread handles 2 cells
    int c0idx = pair * 2;

    float local = 0.0f;
    if (c0idx < n_cells) {
        // y_pre: 2 cells = 20 floats = 80 B, 16B-aligned -> 5x LDG.128
        const float4* gp = (const float4*)(y_pre + (size_t)pair * 20);
        float4 a0 = __ldcs(gp + 0);
        float4 a1 = __ldcs(gp + 1);
        float4 a2 = __ldcs(gp + 2);
        float4 a3 = __ldcs(gp + 3);
        float4 a4 = __ldcs(gp + 4);

        // y_true: 2 cells = 10 floats = 40 B, 8B-aligned -> 5x LDG.64
        const float2* gt = (const float2*)(y_true + (size_t)pair * 10);
        float2 b0 = __ldcs(gt + 0);
        float2 b1 = __ldcs(gt + 1);
        float2 b2 = __ldcs(gt + 2);
        float2 b3 = __ldcs(gt + 3);
        float2 b4 = __ldcs(gt + 4);

        // cell 0: pre = a0.x a0.y a0.z a0.w a1.x | a1.y a1.z a1.w a2.x a2.y
        //         true = b0.x b0.y b1.x b1.y b2.x
        local = cell_loss(a0.x, a0.y, a0.z, a0.w, a1.x,
                          a1.y, a1.z, a1.w, a2.x, a2.y,
                          b0.x, b0.y, b1.x, b1.y, b2.x, c0idx);

        // cell 1: pre = a2.z a2.w a3.x a3.y a3.z | a3.w a4.x a4.y a4.z a4.w
        //         true = b2.y b3.x b3.y b4.x b4.y
        if (c0idx + 1 < n_cells)
            local += cell_loss(a2.z, a2.w, a3.x, a3.y, a3.z,
                               a3.w, a4.x, a4.y, a4.z, a4.w,
                               b2.y, b3.x, b3.y, b4.x, b4.y, c0idx + 1);
    }

    // ---- block reduction (fp32) ----
    #pragma unroll
    for (int off = 16; off > 0; off >>= 1)
        local += __shfl_down_sync(0xFFFFFFFFu, local, off);

    __shared__ float warp_sums[NTHREADS / 32];
    __shared__ bool s_is_last;
    int lane = tid & 31;
    int wid = tid >> 5;
    if (lane == 0) warp_sums[wid] = local;
    __syncthreads();

    if (tid == 0) {
        float v = 0.0f;
        #pragma unroll
        for (int i = 0; i < NTHREADS / 32; i++) v += warp_sums[i];
        atomicAdd(&g_acc, (double)v);
        __threadfence();
        unsigned int prev = atomicInc(&g_ticket, 0xFFFFFFFFu);
        s_is_last = (prev == gridDim.x - 1);
    }
    __syncthreads();

    // ---- last block finalizes & resets state for next graph replay ----
    if (s_is_last && tid == 0) {
        double v = atomicAdd(&g_acc, 0.0);   // coherent read via L2
        out[0] = (float)(v * (double)inv_b);
        g_acc = 0.0;
        __threadfence();
        g_ticket = 0;
    }
}

extern "C" void kernel_launch(void* const* d_in, const int* in_sizes, int n_in,
                              void* d_out, int out_size) {
    const float* y_pre = (const float*)d_in[0];
    const float* y_true = (const float*)d_in[1];
    float* out = (float*)d_out;

    int n_cells = in_sizes[1] / 5;               // B * 49
    int B = n_cells / CELLS_PER_IMG;

    int n_pairs = (n_cells + 1) / 2;
    int grid = (n_pairs + NTHREADS - 1) / NTHREADS;
    yolo_loss_fused<<<grid, NTHREADS>>>(y_pre, y_true, n_cells,
                                        1.0f / (float)B, out);
}

// round 6
// speedup vs baseline: 1.2291x; 1.1782x over previous
#include <cuda_runtime.h>

#define GRID_NUM 7
#define CELLS_PER_IMG 49
#define IMG_SIZE 448.0f
#define GRID_SIZE 64.0f
#define LAMBDA_COORD 5.0f
#define LAMBDA_NOOBJ 0.1f
#define EPSF 1e-12f

#define NTHREADS 256

__device__ double g_acc;   // zero-init in cubin; reset by finalize each launch

__device__ __forceinline__ float iou_f(float bx, float by, float bw, float bh,
                                       float tx, float ty, float tw, float th,
                                       float gi, float gj) {
    float ox = gj * GRID_SIZE;
    float oy = gi * GRID_SIZE;
    float cx_p = fmaf(bx, GRID_SIZE, ox);
    float cy_p = fmaf(by, GRID_SIZE, oy);
    float w_p = bw * IMG_SIZE;
    float h_p = bh * IMG_SIZE;
    float x0p = cx_p - w_p * 0.5f, x1p = cx_p + w_p * 0.5f;
    float y0p = cy_p - h_p * 0.5f, y1p = cy_p + h_p * 0.5f;
    float cx_t = fmaf(tx, GRID_SIZE, ox);
    float cy_t = fmaf(ty, GRID_SIZE, oy);
    float w_t = tw * IMG_SIZE;
    float h_t = th * IMG_SIZE;
    float x0t = cx_t - w_t * 0.5f, x1t = cx_t + w_t * 0.5f;
    float y0t = cy_t - h_t * 0.5f;
    float y1t = cy_t + w_t * 0.5f;   // TYPO kept from reference: uses w_t
    float ux0 = fmaxf(x0p, x0t);
    float ux1 = fminf(x1p, x1t);
    float uy0 = fmaxf(y0p, y0t);
    float uy1 = fminf(y1p, y1t);
    bool valid = (ux0 < ux1) && (uy0 < uy1);
    float area_u = (ux1 - ux0) * (uy1 - uy0);
    float area_p = (x1p - x0p) * (y1p - y0p);
    float area_t = (x1t - x0t) * (y1t - y0t);
    // fast division: MUFU.RCP-based, ~2^-22 rel err (tolerance is 1e-3)
    float res = __fdividef(area_u, area_p + area_t - area_u + EPSF);
    return valid ? res : 0.0f;
}

__global__ void __launch_bounds__(NTHREADS)
yolo_loss_main(const float* __restrict__ y_pre,
               const float* __restrict__ y_true,
               int n_cells) {
    int tid = threadIdx.x;
    int idx = blockIdx.x * NTHREADS + tid;

    float local = 0.0f;
    if (idx < n_cells) {
        int g = idx % CELLS_PER_IMG;
        float gi = (float)(g / GRID_NUM);
        float gj = (float)(g % GRID_NUM);

        // y_pre cell: 10 floats, 40B stride -> 8B aligned -> float2 loads
        const float2* p = (const float2*)(y_pre + (size_t)idx * 10);
        float2 p01 = p[0];
        float2 p23 = p[1];
        float2 p45 = p[2];
        float2 p67 = p[3];
        float2 p89 = p[4];

        const float* t = y_true + (size_t)idx * 5;
        float t0 = t[0], t1 = t[1], t2 = t[2], t3 = t[3], t4 = t[4];

        float iou0 = iou_f(p01.x, p01.y, p23.x, p23.y, t0, t1, t2, t3, gi, gj);
        float iou1 = iou_f(p45.y, p67.x, p67.y, p89.x, t0, t1, t2, t3, gi, gj);

        bool obj = (t4 == 1.0f);
        bool c0 = iou0 > iou1;

        if (obj) {
            float conf_pre = c0 ? p45.x : p89.y;
            float conf_true = c0 ? iou0 : iou1;
            float dc = conf_pre - conf_true;
            local = dc * dc;
            float xb = c0 ? p01.x : p45.y;
            float yb = c0 ? p01.y : p67.x;
            float dx = xb - t0;
            float dy = yb - t1;
            local += LAMBDA_COORD * (dx * dx + dy * dy);
            float wb = fmaxf(c0 ? p23.x : p67.y, EPSF);
            float hb = fmaxf(c0 ? p23.y : p89.x, EPSF);
            float wt = fmaxf(t2, EPSF);
            float ht = fmaxf(t3, EPSF);
            float dw = sqrtf(wb) - sqrtf(wt);
            float dh = sqrtf(hb) - sqrtf(ht);
            local += LAMBDA_COORD * (dw * dw + dh * dh);
        } else {
            local = LAMBDA_NOOBJ * (p45.x * p45.x + p89.y * p89.y);
        }
    }

    // ---- block reduction (fp32) ----
    #pragma unroll
    for (int off = 16; off > 0; off >>= 1)
        local += __shfl_down_sync(0xFFFFFFFFu, local, off);

    __shared__ float warp_sums[NTHREADS / 32];
    int lane = tid & 31;
    int wid = tid >> 5;
    if (lane == 0) warp_sums[wid] = local;
    __syncthreads();

    if (wid == 0) {
        float v = (lane < NTHREADS / 32) ? warp_sums[lane] : 0.0f;
        #pragma unroll
        for (int off = 4; off > 0; off >>= 1)
            v += __shfl_down_sync(0xFFFFFFFFu, v, off);
        if (lane == 0)
            atomicAdd(&g_acc, (double)v);
    }
}

__global__ void finalize_kernel(float* __restrict__ out, float inv_b) {
    // single thread: read accumulated sum, scale, write, reset for next replay
    out[0] = (float)(g_acc * (double)inv_b);
    g_acc = 0.0;
}

extern "C" void kernel_launch(void* const* d_in, const int* in_sizes, int n_in,
                              void* d_out, int out_size) {
    const float* y_pre = (const float*)d_in[0];
    const float* y_true = (const float*)d_in[1];
    float* out = (float*)d_out;

    int n_cells = in_sizes[1] / 5;               // B * 49
    int B = n_cells / CELLS_PER_IMG;

    int grid = (n_cells + NTHREADS - 1) / NTHREADS;
    yolo_loss_main<<<grid, NTHREADS>>>(y_pre, y_true, n_cells);
    finalize_kernel<<<1, 1>>>(out, 1.0f / (float)B);
}